// round 15
// baseline (speedup 1.0000x reference)
#include <cuda_runtime.h>
#include <cuda_fp16.h>
#include <cstdint>

// ToeplitzLinear: D[m,n] = sum_k X[m,k] * vals[4095 - n + k]
// R15: R12 mainloop (2-stage warp-private cp.async ring, plain-store epilogue)
// + two m-tiles per CTA (amortized sv staging / prologue, 3.5 waves)
// + half-1 prologue issued under half-0 epilogue. Conflict-free prepass (R14).

#define M_DIM 8192
#define N_DIM 4096
#define K_DIM 4096
#define BM 128
#define BN 128
#define BK 64
#define NITER (K_DIM / BK)       // 64
#define THREADS 256

#define VWIN_WORDS 4224
#define WSTAGE_BYTES 4096        // per warp per stage: 2 rb x 4 ks x 32 x 16B
#define SV_OFF 65536             // 8 warps x 2 stages x 4KB
#define SMEM_TOTAL (SV_OFF + VWIN_WORDS * 4)   // 82432

__device__ uint32_t g_xh[(size_t)M_DIM * K_DIM / 2];
__device__ uint32_t g_v2h[8192];   // g_v2h[i] = half2(w[i], w[i+1]), w = fp16(vals)

__device__ __forceinline__ uint32_t smem_u32(const void* p) {
    uint32_t a;
    asm("{ .reg .u64 t; cvta.to.shared.u64 t, %1; cvt.u32.u64 %0, t; }"
        : "=r"(a) : "l"(p));
    return a;
}
__device__ __forceinline__ void cp16(uint32_t saddr, const void* g) {
    asm volatile("cp.async.cg.shared.global [%0], [%1], 16;"
                 :: "r"(saddr), "l"(g) : "memory");
}
__device__ __forceinline__ void cp_commit() {
    asm volatile("cp.async.commit_group;" ::: "memory");
}
template <int N>
__device__ __forceinline__ void cp_wait() {
    asm volatile("cp.async.wait_group %0;" :: "n"(N) : "memory");
}
__device__ __forceinline__ void mma_fp16(float c[4], uint32_t a0, uint32_t a1,
                                         uint32_t a2, uint32_t a3,
                                         uint32_t b0, uint32_t b1) {
    asm volatile(
        "mma.sync.aligned.m16n8k16.row.col.f32.f16.f16.f32 "
        "{%0,%1,%2,%3}, {%4,%5,%6,%7}, {%8,%9}, {%0,%1,%2,%3};"
        : "+f"(c[0]), "+f"(c[1]), "+f"(c[2]), "+f"(c[3])
        : "r"(a0), "r"(a1), "r"(a2), "r"(a3), "r"(b0), "r"(b1));
}
__device__ __forceinline__ uint32_t pack_h2(float a, float b) {
    __half2 h = __floats2half2_rn(a, b);
    return *reinterpret_cast<uint32_t*>(&h);
}

// ---- pre-pass: X -> fp16 fragment-shuffled (conflict-free, R14) ----
#define PREROW 132
__global__ void __launch_bounds__(256) cvt_x_kernel(const float* __restrict__ x,
                                                    const float* __restrict__ v) {
    __shared__ float sm[32 * PREROW];
    const int tid = threadIdx.x;
    const int r0 = blockIdx.y * 32;
    const int c0 = blockIdx.x * 128;

    if (blockIdx.x == 0 && blockIdx.y == 0) {
        for (int i = tid; i < 8192; i += 256) {
            float a = (i < 8191) ? v[i] : 0.0f;
            float b = (i + 1 < 8191) ? v[i + 1] : 0.0f;
            g_v2h[i] = pack_h2(a, b);
        }
    }
#pragma unroll
    for (int i = 0; i < 4; i++) {
        const int f = tid + 256 * i;
        const int r = f >> 5;
        const int cq = f & 31;
        float4 vv = *reinterpret_cast<const float4*>(
            x + (size_t)(r0 + r) * K_DIM + c0 + 4 * cq);
        *reinterpret_cast<float4*>(sm + r * PREROW + 4 * cq) = vv;
    }
    __syncthreads();
    {
        const int p = tid;
        const int tile = p >> 7;
        const int cb = (p >> 4) & 7;
        const int g = p & 7;
        const int h = (p >> 3) & 1;
        const float* base = sm + tile * 16 * PREROW + 16 * cb + 4 * h;
        float4 X0 = *reinterpret_cast<const float4*>(base + g * PREROW);
        float4 Y0 = *reinterpret_cast<const float4*>(base + (g + 8) * PREROW);
        float4 Z0 = *reinterpret_cast<const float4*>(base + g * PREROW + 8);
        float4 W0 = *reinterpret_cast<const float4*>(base + (g + 8) * PREROW + 8);

        const size_t rb = (size_t)(blockIdx.y * 2 + tile);
        const size_t cbg = (size_t)blockIdx.x * 8 + cb;
        uint32_t* dst = g_xh + (rb * 256 + cbg) * 128;

        const int l1 = g * 4 + 2 * h;
        uint4 u1;
        u1.x = pack_h2(X0.x, X0.y);
        u1.y = pack_h2(Y0.x, Y0.y);
        u1.z = pack_h2(Z0.x, Z0.y);
        u1.w = pack_h2(W0.x, W0.y);
        *reinterpret_cast<uint4*>(dst + l1 * 4) = u1;

        uint4 u2;
        u2.x = pack_h2(X0.z, X0.w);
        u2.y = pack_h2(Y0.z, Y0.w);
        u2.z = pack_h2(Z0.z, Z0.w);
        u2.w = pack_h2(W0.z, W0.w);
        *reinterpret_cast<uint4*>(dst + (l1 + 1) * 4) = u2;
    }
}

// Stage one iter's A tile for this warp: 8 cp.async.16 per lane.
__device__ __forceinline__ void issue_a(int u, uint32_t wstage,
                                        const uint32_t* g0, const uint32_t* g1,
                                        int lane) {
#pragma unroll
    for (int i = 0; i < 8; i++) {
        const int mm = i >> 2;
        const int ks = i & 3;
        const uint32_t* src = (mm ? g1 : g0) + (size_t)(4 * u + ks) * 128;
        cp16(wstage + i * 512 + lane * 16, src);
    }
}

__global__ void __launch_bounds__(THREADS, 2)
toeplitz_mma_kernel(float* __restrict__ out) {
    extern __shared__ char smem[];
    uint32_t* sv = reinterpret_cast<uint32_t*>(smem + SV_OFF);

    const int tid = threadIdx.x;
    const int wid = tid >> 5;
    const int lane = tid & 31;
    const int g = lane >> 2;
    const int tig = lane & 3;
    const int warpM = wid & 3;
    const int warpN = wid >> 2;

    const int n0 = blockIdx.x * BN;
    const int vbase = 3968 - n0;

    // stage the whole vals pair-window once (serves both m-halves)
    {
        const uint4* src = reinterpret_cast<const uint4*>(g_v2h + vbase);
        uint4* dst = reinterpret_cast<uint4*>(sv);
        for (int i = tid; i < VWIN_WORDS / 4; i += THREADS) dst[i] = src[i];
    }

    const uint32_t swb = smem_u32(smem) + wid * (2 * WSTAGE_BYTES);
    const int Q = 2 * tig - g + 71 - warpN * 64;   // [0,77]

    // per-half A gmem bases
    const int m0_0 = blockIdx.y * (2 * BM);
    const uint32_t* g0h[2], * g1h[2];
#pragma unroll
    for (int hf = 0; hf < 2; hf++) {
        const int m0 = m0_0 + hf * BM;
        g0h[hf] = g_xh + ((size_t)((m0 >> 4) + warpM * 2 + 0) * 256) * 128 + lane * 4;
        g1h[hf] = g_xh + ((size_t)((m0 >> 4) + warpM * 2 + 1) * 256) * 128 + lane * 4;
    }

    // prologue for half 0
    issue_a(0, swb, g0h[0], g1h[0], lane);
    cp_commit();
    issue_a(1, swb + WSTAGE_BYTES, g0h[0], g1h[0], lane);
    cp_commit();

    __syncthreads();   // sv ready; only CTA-wide barrier

#pragma unroll 1
    for (int hf = 0; hf < 2; hf++) {
        const uint32_t* g0 = g0h[hf];
        const uint32_t* g1 = g1h[hf];

        float acc[2][8][4];
#pragma unroll
        for (int mm = 0; mm < 2; mm++)
#pragma unroll
            for (int nn = 0; nn < 8; nn++)
#pragma unroll
                for (int r = 0; r < 4; r++) acc[mm][nn][r] = 0.0f;

#pragma unroll 1
        for (int t = 0; t < NITER; t++) {
            cp_wait<1>();

            const uint32_t* vp = sv + 64 * t + Q;
            uint32_t Bf[15];
#pragma unroll
            for (int e = 0; e < 15; e++) Bf[e] = vp[8 * e];

            const char* wb = smem + wid * (2 * WSTAGE_BYTES) +
                             (t & 1) * WSTAGE_BYTES;
            uint4 a0[4], a1[4];
#pragma unroll
            for (int ks = 0; ks < 4; ks++)
                a0[ks] = *reinterpret_cast<const uint4*>(wb + ks * 512 + lane * 16);
#pragma unroll
            for (int ks = 0; ks < 4; ks++)
                a1[ks] = *reinterpret_cast<const uint4*>(wb + (4 + ks) * 512 + lane * 16);

#pragma unroll
            for (int ks = 0; ks < 4; ks++)
#pragma unroll
                for (int nn = 0; nn < 8; nn++) {
                    const int e = 2 * ks - nn + 7;
                    mma_fp16(acc[0][nn], a0[ks].x, a0[ks].y, a0[ks].z, a0[ks].w,
                             Bf[e], Bf[e + 1]);
                    mma_fp16(acc[1][nn], a1[ks].x, a1[ks].y, a1[ks].z, a1[ks].w,
                             Bf[e], Bf[e + 1]);
                }

            // refill: iters t+2 of this half; last two iters pre-stage the
            // NEXT half's iters 0,1 (keeps FIFO cadence: 1 commit per iter)
            if (t + 2 < NITER) {
                issue_a(t + 2, swb + (t & 1) * WSTAGE_BYTES, g0, g1, lane);
            } else if (hf == 0) {
                issue_a(t + 2 - NITER, swb + (t & 1) * WSTAGE_BYTES,
                        g0h[1], g1h[1], lane);
            }
            cp_commit();
        }

        // epilogue for this half (half-1's first stages already in flight)
        const int m0 = m0_0 + hf * BM;
#pragma unroll
        for (int mm = 0; mm < 2; mm++) {
            const int row = m0 + warpM * 32 + mm * 16 + g;
#pragma unroll
            for (int nn = 0; nn < 8; nn++) {
                const int col = n0 + warpN * 64 + nn * 8 + tig * 2;
                *reinterpret_cast<float2*>(out + (size_t)row * N_DIM + col) =
                    make_float2(acc[mm][nn][0], acc[mm][nn][1]);
                *reinterpret_cast<float2*>(out + (size_t)(row + 8) * N_DIM + col) =
                    make_float2(acc[mm][nn][2], acc[mm][nn][3]);
            }
        }
    }
}

extern "C" void kernel_launch(void* const* d_in, const int* in_sizes, int n_in,
                              void* d_out, int out_size) {
    const float* x    = (const float*)d_in[0];
    const float* vals = (const float*)d_in[1];
    float* out        = (float*)d_out;

    static int attr_set = 0;
    if (!attr_set) {
        cudaFuncSetAttribute(toeplitz_mma_kernel,
                             cudaFuncAttributeMaxDynamicSharedMemorySize,
                             SMEM_TOTAL);
        attr_set = 1;
    }

    cvt_x_kernel<<<dim3(K_DIM / 128, M_DIM / 32), 256>>>(x, vals);

    dim3 grid(N_DIM / BN, M_DIM / (2 * BM));   // 32 x 32, two m-tiles per CTA
    toeplitz_mma_kernel<<<grid, THREADS, SMEM_TOTAL>>>(out);
}

// round 16
// speedup vs baseline: 1.0116x; 1.0116x over previous
#include <cuda_runtime.h>
#include <cuda_fp16.h>
#include <cstdint>

// ToeplitzLinear: D[m,n] = sum_k X[m,k] * vals[4095 - n + k]
// R16: rolling register pipeline. 3-stage warp-private cp.async ring with the
// wait at iter END (stages t and t+1 both resident inside iter t), A-fragment
// LDS rolled one ks ahead (crossing the iter boundary into stage t+1), Bf
// double-buffered and loaded one iter ahead. Barrier-free; R14 prepass.

#define M_DIM 8192
#define N_DIM 4096
#define K_DIM 4096
#define BM 128
#define BN 128
#define BK 64
#define NITER (K_DIM / BK)       // 64
#define THREADS 256

#define VWIN_WORDS 4224
#define WSTAGE_BYTES 4096        // per warp per stage: 2 mm x 4 ks x 32 x 16B
#define NSTAGE 3
#define SV_OFF (8 * NSTAGE * WSTAGE_BYTES)      // 98304
#define SMEM_TOTAL (SV_OFF + VWIN_WORDS * 4)    // 115200

__device__ uint32_t g_xh[(size_t)M_DIM * K_DIM / 2];
__device__ uint32_t g_v2h[8192];   // g_v2h[i] = half2(w[i], w[i+1])

__device__ __forceinline__ uint32_t smem_u32(const void* p) {
    uint32_t a;
    asm("{ .reg .u64 t; cvta.to.shared.u64 t, %1; cvt.u32.u64 %0, t; }"
        : "=r"(a) : "l"(p));
    return a;
}
__device__ __forceinline__ void cp16(uint32_t saddr, const void* g) {
    asm volatile("cp.async.cg.shared.global [%0], [%1], 16;"
                 :: "r"(saddr), "l"(g) : "memory");
}
__device__ __forceinline__ void cp_commit() {
    asm volatile("cp.async.commit_group;" ::: "memory");
}
template <int N>
__device__ __forceinline__ void cp_wait() {
    asm volatile("cp.async.wait_group %0;" :: "n"(N) : "memory");
}
__device__ __forceinline__ void mma_fp16(float c[4], uint32_t a0, uint32_t a1,
                                         uint32_t a2, uint32_t a3,
                                         uint32_t b0, uint32_t b1) {
    asm volatile(
        "mma.sync.aligned.m16n8k16.row.col.f32.f16.f16.f32 "
        "{%0,%1,%2,%3}, {%4,%5,%6,%7}, {%8,%9}, {%0,%1,%2,%3};"
        : "+f"(c[0]), "+f"(c[1]), "+f"(c[2]), "+f"(c[3])
        : "r"(a0), "r"(a1), "r"(a2), "r"(a3), "r"(b0), "r"(b1));
}
__device__ __forceinline__ uint32_t pack_h2(float a, float b) {
    __half2 h = __floats2half2_rn(a, b);
    return *reinterpret_cast<uint32_t*>(&h);
}

// ---- pre-pass: X -> fp16 fragment-shuffled (conflict-free, R14) ----
#define PREROW 132
__global__ void __launch_bounds__(256) cvt_x_kernel(const float* __restrict__ x,
                                                    const float* __restrict__ v) {
    __shared__ float sm[32 * PREROW];
    const int tid = threadIdx.x;
    const int r0 = blockIdx.y * 32;
    const int c0 = blockIdx.x * 128;

    if (blockIdx.x == 0 && blockIdx.y == 0) {
        for (int i = tid; i < 8192; i += 256) {
            float a = (i < 8191) ? v[i] : 0.0f;
            float b = (i + 1 < 8191) ? v[i + 1] : 0.0f;
            g_v2h[i] = pack_h2(a, b);
        }
    }
#pragma unroll
    for (int i = 0; i < 4; i++) {
        const int f = tid + 256 * i;
        const int r = f >> 5;
        const int cq = f & 31;
        float4 vv = *reinterpret_cast<const float4*>(
            x + (size_t)(r0 + r) * K_DIM + c0 + 4 * cq);
        *reinterpret_cast<float4*>(sm + r * PREROW + 4 * cq) = vv;
    }
    __syncthreads();
    {
        const int p = tid;
        const int tile = p >> 7;
        const int cb = (p >> 4) & 7;
        const int g = p & 7;
        const int h = (p >> 3) & 1;
        const float* base = sm + tile * 16 * PREROW + 16 * cb + 4 * h;
        float4 X0 = *reinterpret_cast<const float4*>(base + g * PREROW);
        float4 Y0 = *reinterpret_cast<const float4*>(base + (g + 8) * PREROW);
        float4 Z0 = *reinterpret_cast<const float4*>(base + g * PREROW + 8);
        float4 W0 = *reinterpret_cast<const float4*>(base + (g + 8) * PREROW + 8);

        const size_t rb = (size_t)(blockIdx.y * 2 + tile);
        const size_t cbg = (size_t)blockIdx.x * 8 + cb;
        uint32_t* dst = g_xh + (rb * 256 + cbg) * 128;

        const int l1 = g * 4 + 2 * h;
        uint4 u1;
        u1.x = pack_h2(X0.x, X0.y);
        u1.y = pack_h2(Y0.x, Y0.y);
        u1.z = pack_h2(Z0.x, Z0.y);
        u1.w = pack_h2(W0.x, W0.y);
        *reinterpret_cast<uint4*>(dst + l1 * 4) = u1;

        uint4 u2;
        u2.x = pack_h2(X0.z, X0.w);
        u2.y = pack_h2(Y0.z, Y0.w);
        u2.z = pack_h2(Z0.z, Z0.w);
        u2.w = pack_h2(W0.z, W0.w);
        *reinterpret_cast<uint4*>(dst + (l1 + 1) * 4) = u2;
    }
}

// Stage one iter's A tile for this warp: 8 cp.async.16 per lane.
__device__ __forceinline__ void issue_a(int u, uint32_t wstage,
                                        const uint32_t* g0, const uint32_t* g1,
                                        int lane) {
#pragma unroll
    for (int i = 0; i < 8; i++) {
        const int mm = i >> 2;
        const int ks = i & 3;
        const uint32_t* src = (mm ? g1 : g0) + (size_t)(4 * u + ks) * 128;
        cp16(wstage + i * 512 + lane * 16, src);
    }
}

__global__ void __launch_bounds__(THREADS, 2)
toeplitz_mma_kernel(float* __restrict__ out) {
    extern __shared__ char smem[];
    uint32_t* sv = reinterpret_cast<uint32_t*>(smem + SV_OFF);

    const int tid = threadIdx.x;
    const int wid = tid >> 5;
    const int lane = tid & 31;
    const int g = lane >> 2;
    const int tig = lane & 3;
    const int warpM = wid & 3;
    const int warpN = wid >> 2;

    const int n0 = blockIdx.x * BN;
    const int m0 = blockIdx.y * BM;
    const int vbase = 3968 - n0;

    // stage the whole vals pair-window once
    {
        const uint4* src = reinterpret_cast<const uint4*>(g_v2h + vbase);
        uint4* dst = reinterpret_cast<uint4*>(sv);
        for (int i = tid; i < VWIN_WORDS / 4; i += THREADS) dst[i] = src[i];
    }

    float acc[2][8][4];
#pragma unroll
    for (int mm = 0; mm < 2; mm++)
#pragma unroll
        for (int nn = 0; nn < 8; nn++)
#pragma unroll
            for (int r = 0; r < 4; r++) acc[mm][nn][r] = 0.0f;

    const uint32_t swb = smem_u32(smem) + wid * (NSTAGE * WSTAGE_BYTES);
    const uint32_t* g0 = g_xh +
        ((size_t)((m0 >> 4) + warpM * 2 + 0) * 256) * 128 + lane * 4;
    const uint32_t* g1 = g_xh +
        ((size_t)((m0 >> 4) + warpM * 2 + 1) * 256) * 128 + lane * 4;

    // prologue: prefetch iters 0..2 into the 3-stage warp-private ring
    issue_a(0, swb, g0, g1, lane);
    cp_commit();
    issue_a(1, swb + WSTAGE_BYTES, g0, g1, lane);
    cp_commit();
    issue_a(2, swb + 2 * WSTAGE_BYTES, g0, g1, lane);
    cp_commit();

    __syncthreads();   // sv ready; only CTA-wide barrier before epilogue

    const int Q = 2 * tig - g + 71 - warpN * 64;   // [0,77]

    cp_wait<1>();      // stages 0 and 1 resident

    // preload: Bf for iter 0, A fragments for (iter 0, ks 0)
    uint32_t Bf[2][15];
#pragma unroll
    for (int e = 0; e < 15; e++) Bf[0][e] = sv[Q + 8 * e];

    uint4 Ar[2][2];    // [slot][mm]
    Ar[0][0] = *reinterpret_cast<const uint4*>(smem + wid * (NSTAGE * WSTAGE_BYTES) + lane * 16);
    Ar[0][1] = *reinterpret_cast<const uint4*>(smem + wid * (NSTAGE * WSTAGE_BYTES) + 2048 + lane * 16);

    int st = 0;
#pragma unroll 2
    for (int t = 0; t < NITER; t++) {
        const int p = t & 1;               // Bf parity (compile-time after unroll)
        const int stn = (st == NSTAGE - 1) ? 0 : st + 1;
        const char* wb_cur = smem + wid * (NSTAGE * WSTAGE_BYTES) + st * WSTAGE_BYTES;
        const char* wb_nxt = smem + wid * (NSTAGE * WSTAGE_BYTES) + stn * WSTAGE_BYTES;

#pragma unroll
        for (int ks = 0; ks < 4; ks++) {
            const int slot = ks & 1;
            const int nslot = slot ^ 1;

            // roll A: load ks+1 (or iter t+1's ks=0 from stage t+1)
            if (ks < 3) {
                Ar[nslot][0] = *reinterpret_cast<const uint4*>(
                    wb_cur + (ks + 1) * 512 + lane * 16);
                Ar[nslot][1] = *reinterpret_cast<const uint4*>(
                    wb_cur + (ks + 1) * 512 + 2048 + lane * 16);
            } else {
                Ar[nslot][0] = *reinterpret_cast<const uint4*>(
                    wb_nxt + lane * 16);
                Ar[nslot][1] = *reinterpret_cast<const uint4*>(
                    wb_nxt + 2048 + lane * 16);
            }
            // roll Bf: next iter's window under ks=0 MMA block
            if (ks == 0 && t + 1 < NITER) {
                const uint32_t* vp = sv + 64 * (t + 1) + Q;
#pragma unroll
                for (int e = 0; e < 15; e++) Bf[p ^ 1][e] = vp[8 * e];
            }

#pragma unroll
            for (int nn = 0; nn < 8; nn++) {
                const int e = 2 * ks - nn + 7;
                mma_fp16(acc[0][nn], Ar[slot][0].x, Ar[slot][0].y,
                         Ar[slot][0].z, Ar[slot][0].w, Bf[p][e], Bf[p][e + 1]);
                mma_fp16(acc[1][nn], Ar[slot][1].x, Ar[slot][1].y,
                         Ar[slot][1].z, Ar[slot][1].w, Bf[p][e], Bf[p][e + 1]);
            }
        }

        // refill the consumed stage with iter t+3
        if (t + 3 < NITER)
            issue_a(t + 3, swb + st * WSTAGE_BYTES, g0, g1, lane);
        cp_commit();
        cp_wait<1>();   // guarantee stages t+1, t+2 resident for next iter

        st = stn;
    }

    // epilogue: plain float2 stores
#pragma unroll
    for (int mm = 0; mm < 2; mm++) {
        const int row = m0 + warpM * 32 + mm * 16 + g;
#pragma unroll
        for (int nn = 0; nn < 8; nn++) {
            const int col = n0 + warpN * 64 + nn * 8 + tig * 2;
            *reinterpret_cast<float2*>(out + (size_t)row * N_DIM + col) =
                make_float2(acc[mm][nn][0], acc[mm][nn][1]);
            *reinterpret_cast<float2*>(out + (size_t)(row + 8) * N_DIM + col) =
                make_float2(acc[mm][nn][2], acc[mm][nn][3]);
        }
    }
}

extern "C" void kernel_launch(void* const* d_in, const int* in_sizes, int n_in,
                              void* d_out, int out_size) {
    const float* x    = (const float*)d_in[0];
    const float* vals = (const float*)d_in[1];
    float* out        = (float*)d_out;

    static int attr_set = 0;
    if (!attr_set) {
        cudaFuncSetAttribute(toeplitz_mma_kernel,
                             cudaFuncAttributeMaxDynamicSharedMemorySize,
                             SMEM_TOTAL);
        attr_set = 1;
    }

    cvt_x_kernel<<<dim3(K_DIM / 128, M_DIM / 32), 256>>>(x, vals);

    dim3 grid(N_DIM / BN, M_DIM / BM);   // 32 x 64
    toeplitz_mma_kernel<<<grid, THREADS, SMEM_TOTAL>>>(out);
}

// round 17
// speedup vs baseline: 1.0271x; 1.0153x over previous
#include <cuda_runtime.h>
#include <cuda_fp16.h>
#include <cstdint>

// ToeplitzLinear: D[m,n] = sum_k X[m,k] * vals[4095 - n + k]
// R17: warp tile m16n64 (acc 32 regs) -> __launch_bounds__(256,3) -> 3 CTAs/SM
// = 6 warps/SMSP to fill tensor-pipe gaps. CTA tile 64x128, 2-stage
// warp-private cp.async ring (R12 loop shape), R14 conflict-free prepass.

#define M_DIM 8192
#define N_DIM 4096
#define K_DIM 4096
#define BM 64
#define BN 128
#define BK 64
#define NITER (K_DIM / BK)       // 64
#define THREADS 256

#define VWIN_WORDS 4224
#define WSTAGE_BYTES 2048        // per warp per stage: 4 ks x 32 lanes x 16B
#define SV_OFF (8 * 2 * WSTAGE_BYTES)           // 32768
#define SMEM_TOTAL (SV_OFF + VWIN_WORDS * 4)    // 49664 (x3 = 149KB/SM)

__device__ uint32_t g_xh[(size_t)M_DIM * K_DIM / 2];
__device__ uint32_t g_v2h[8192];   // g_v2h[i] = half2(w[i], w[i+1])

__device__ __forceinline__ uint32_t smem_u32(const void* p) {
    uint32_t a;
    asm("{ .reg .u64 t; cvta.to.shared.u64 t, %1; cvt.u32.u64 %0, t; }"
        : "=r"(a) : "l"(p));
    return a;
}
__device__ __forceinline__ void cp16(uint32_t saddr, const void* g) {
    asm volatile("cp.async.cg.shared.global [%0], [%1], 16;"
                 :: "r"(saddr), "l"(g) : "memory");
}
__device__ __forceinline__ void cp_commit() {
    asm volatile("cp.async.commit_group;" ::: "memory");
}
template <int N>
__device__ __forceinline__ void cp_wait() {
    asm volatile("cp.async.wait_group %0;" :: "n"(N) : "memory");
}
__device__ __forceinline__ void mma_fp16(float c[4], uint32_t a0, uint32_t a1,
                                         uint32_t a2, uint32_t a3,
                                         uint32_t b0, uint32_t b1) {
    asm volatile(
        "mma.sync.aligned.m16n8k16.row.col.f32.f16.f16.f32 "
        "{%0,%1,%2,%3}, {%4,%5,%6,%7}, {%8,%9}, {%0,%1,%2,%3};"
        : "+f"(c[0]), "+f"(c[1]), "+f"(c[2]), "+f"(c[3])
        : "r"(a0), "r"(a1), "r"(a2), "r"(a3), "r"(b0), "r"(b1));
}
__device__ __forceinline__ uint32_t pack_h2(float a, float b) {
    __half2 h = __floats2half2_rn(a, b);
    return *reinterpret_cast<uint32_t*>(&h);
}

// ---- pre-pass: X -> fp16 fragment-shuffled (conflict-free, R14) ----
#define PREROW 132
__global__ void __launch_bounds__(256) cvt_x_kernel(const float* __restrict__ x,
                                                    const float* __restrict__ v) {
    __shared__ float sm[32 * PREROW];
    const int tid = threadIdx.x;
    const int r0 = blockIdx.y * 32;
    const int c0 = blockIdx.x * 128;

    if (blockIdx.x == 0 && blockIdx.y == 0) {
        for (int i = tid; i < 8192; i += 256) {
            float a = (i < 8191) ? v[i] : 0.0f;
            float b = (i + 1 < 8191) ? v[i + 1] : 0.0f;
            g_v2h[i] = pack_h2(a, b);
        }
    }
#pragma unroll
    for (int i = 0; i < 4; i++) {
        const int f = tid + 256 * i;
        const int r = f >> 5;
        const int cq = f & 31;
        float4 vv = *reinterpret_cast<const float4*>(
            x + (size_t)(r0 + r) * K_DIM + c0 + 4 * cq);
        *reinterpret_cast<float4*>(sm + r * PREROW + 4 * cq) = vv;
    }
    __syncthreads();
    {
        const int p = tid;
        const int tile = p >> 7;
        const int cb = (p >> 4) & 7;
        const int g = p & 7;
        const int h = (p >> 3) & 1;
        const float* base = sm + tile * 16 * PREROW + 16 * cb + 4 * h;
        float4 X0 = *reinterpret_cast<const float4*>(base + g * PREROW);
        float4 Y0 = *reinterpret_cast<const float4*>(base + (g + 8) * PREROW);
        float4 Z0 = *reinterpret_cast<const float4*>(base + g * PREROW + 8);
        float4 W0 = *reinterpret_cast<const float4*>(base + (g + 8) * PREROW + 8);

        const size_t rb = (size_t)(blockIdx.y * 2 + tile);
        const size_t cbg = (size_t)blockIdx.x * 8 + cb;
        uint32_t* dst = g_xh + (rb * 256 + cbg) * 128;

        const int l1 = g * 4 + 2 * h;
        uint4 u1;
        u1.x = pack_h2(X0.x, X0.y);
        u1.y = pack_h2(Y0.x, Y0.y);
        u1.z = pack_h2(Z0.x, Z0.y);
        u1.w = pack_h2(W0.x, W0.y);
        *reinterpret_cast<uint4*>(dst + l1 * 4) = u1;

        uint4 u2;
        u2.x = pack_h2(X0.z, X0.w);
        u2.y = pack_h2(Y0.z, Y0.w);
        u2.z = pack_h2(Z0.z, Z0.w);
        u2.w = pack_h2(W0.z, W0.w);
        *reinterpret_cast<uint4*>(dst + (l1 + 1) * 4) = u2;
    }
}

// Stage one iter's A tile for this warp (1 rb): 4 cp.async.16 per lane.
__device__ __forceinline__ void issue_a(int u, uint32_t wstage,
                                        const uint32_t* g0, int lane) {
#pragma unroll
    for (int ks = 0; ks < 4; ks++) {
        const uint32_t* src = g0 + (size_t)(4 * u + ks) * 128;
        cp16(wstage + ks * 512 + lane * 16, src);
    }
}

__global__ void __launch_bounds__(THREADS, 3)
toeplitz_mma_kernel(float* __restrict__ out) {
    extern __shared__ char smem[];
    uint32_t* sv = reinterpret_cast<uint32_t*>(smem + SV_OFF);

    const int tid = threadIdx.x;
    const int wid = tid >> 5;
    const int lane = tid & 31;
    const int g = lane >> 2;
    const int tig = lane & 3;
    const int warpM = wid & 3;     // 4 m-slots x 16 rows
    const int warpN = wid >> 2;    // 2 n-slots x 64 cols

    const int n0 = blockIdx.x * BN;
    const int m0 = blockIdx.y * BM;
    const int vbase = 3968 - n0;

    // stage the whole vals pair-window once
    {
        const uint4* src = reinterpret_cast<const uint4*>(g_v2h + vbase);
        uint4* dst = reinterpret_cast<uint4*>(sv);
        for (int i = tid; i < VWIN_WORDS / 4; i += THREADS) dst[i] = src[i];
    }

    float acc[8][4];
#pragma unroll
    for (int nn = 0; nn < 8; nn++)
#pragma unroll
        for (int r = 0; r < 4; r++) acc[nn][r] = 0.0f;

    const uint32_t swb = smem_u32(smem) + wid * (2 * WSTAGE_BYTES);
    const uint32_t* g0 = g_xh +
        ((size_t)((m0 >> 4) + warpM) * 256) * 128 + lane * 4;

    issue_a(0, swb, g0, lane);
    cp_commit();
    issue_a(1, swb + WSTAGE_BYTES, g0, lane);
    cp_commit();

    __syncthreads();   // sv ready; only CTA-wide barrier before epilogue

    const int Q = 2 * tig - g + 71 - warpN * 64;   // [0,77]

#pragma unroll 1
    for (int t = 0; t < NITER; t++) {
        cp_wait<1>();

        const uint32_t* vp = sv + 64 * t + Q;
        uint32_t Bf[15];
#pragma unroll
        for (int e = 0; e < 15; e++) Bf[e] = vp[8 * e];

        const char* wb = smem + wid * (2 * WSTAGE_BYTES) + (t & 1) * WSTAGE_BYTES;
        uint4 a[4];
#pragma unroll
        for (int ks = 0; ks < 4; ks++)
            a[ks] = *reinterpret_cast<const uint4*>(wb + ks * 512 + lane * 16);

#pragma unroll
        for (int ks = 0; ks < 4; ks++)
#pragma unroll
            for (int nn = 0; nn < 8; nn++) {
                const int e = 2 * ks - nn + 7;
                mma_fp16(acc[nn], a[ks].x, a[ks].y, a[ks].z, a[ks].w,
                         Bf[e], Bf[e + 1]);
            }

        if (t + 2 < NITER)
            issue_a(t + 2, swb + (t & 1) * WSTAGE_BYTES, g0, lane);
        cp_commit();
    }

    // epilogue: plain float2 stores
    {
        const int row = m0 + warpM * 16 + g;
#pragma unroll
        for (int nn = 0; nn < 8; nn++) {
            const int col = n0 + warpN * 64 + nn * 8 + tig * 2;
            *reinterpret_cast<float2*>(out + (size_t)row * N_DIM + col) =
                make_float2(acc[nn][0], acc[nn][1]);
            *reinterpret_cast<float2*>(out + (size_t)(row + 8) * N_DIM + col) =
                make_float2(acc[nn][2], acc[nn][3]);
        }
    }
}

extern "C" void kernel_launch(void* const* d_in, const int* in_sizes, int n_in,
                              void* d_out, int out_size) {
    const float* x    = (const float*)d_in[0];
    const float* vals = (const float*)d_in[1];
    float* out        = (float*)d_out;

    static int attr_set = 0;
    if (!attr_set) {
        cudaFuncSetAttribute(toeplitz_mma_kernel,
                             cudaFuncAttributeMaxDynamicSharedMemorySize,
                             SMEM_TOTAL);
        attr_set = 1;
    }

    cvt_x_kernel<<<dim3(K_DIM / 128, M_DIM / 32), 256>>>(x, vals);

    dim3 grid(N_DIM / BN, M_DIM / BM);   // 32 x 128
    toeplitz_mma_kernel<<<grid, THREADS, SMEM_TOTAL>>>(out);
}